// round 9
// baseline (speedup 1.0000x reference)
#include <cuda_runtime.h>
#include <cstdint>

#define HH 512
#define WW 512
#define WORDS 16
#define SLAB 128
#define HALO 3
#define NTH 512
#define NOFF 12
#define SLABS (HH / SLAB)
#define CROWS 8                        // rows per chunk
#define NCHUNK (SLAB / CROWS)          // 16
#define CFLOATS (CROWS * WW)           // 4096 floats = 16KB
#define CBYTES (CFLOATS * 4)
#define NSTAGE 4
#define BITS_WORDS ((SLAB + HALO) * WORDS + WORDS)   // 2112 (incl. guard)
#define MAXB 128

// zero-initialized; every use paired with a reset -> deterministic graph replays
__device__ int g_cnt[MAXB * NOFF * 2];     // [image][offset]{diff, n11}
__device__ unsigned g_arrive[MAXB];

__device__ __forceinline__ void mbar_init(unsigned a, unsigned cnt) {
    asm volatile("mbarrier.init.shared.b64 [%0], %1;" :: "r"(a), "r"(cnt) : "memory");
}
__device__ __forceinline__ void mbar_expect_tx(unsigned a, unsigned bytes) {
    asm volatile("mbarrier.arrive.expect_tx.shared.b64 _, [%0], %1;"
                 :: "r"(a), "r"(bytes) : "memory");
}
__device__ __forceinline__ void bulk_g2s(unsigned dst, const float* src,
                                         unsigned bytes, unsigned mbar) {
    asm volatile("cp.async.bulk.shared::cluster.global.mbarrier::complete_tx::bytes "
                 "[%0], [%1], %2, [%3];"
                 :: "r"(dst), "l"(src), "r"(bytes), "r"(mbar) : "memory");
}
__device__ __forceinline__ void mbar_wait(unsigned a, unsigned parity) {
    asm volatile(
        "{\n\t"
        ".reg .pred P1;\n\t"
        "WAIT_LOOP_%=:\n\t"
        "mbarrier.try_wait.parity.shared.b64 P1, [%0], %1;\n\t"
        "@P1 bra.uni WAIT_DONE_%=;\n\t"
        "bra.uni WAIT_LOOP_%=;\n\t"
        "WAIT_DONE_%=:\n\t"
        "}"
        :: "r"(a), "r"(parity) : "memory");
}

// count 3 offsets (group G) over a-rows [from, to), this thread's word column
template<int G>
__device__ __forceinline__ void count_window(
    const unsigned* __restrict__ bits, int from, int to,
    int rowoff, int word, const int* __restrict__ rl, unsigned* __restrict__ acc)
{
    constexpr int RS[NOFF] = {0, 1, 1, 1, 0, 2, 2, 2, 0, 3, 3, 3};
    constexpr int CS[NOFF] = {1, 1, 0, -1, 2, 2, 0, -2, 3, 3, 0, -3};
    const bool firstw = (word == 0);
    const bool lastw  = (word == WORDS - 1);

    // first r >= from with r % 8 == rowoff
    int r = ((from - rowoff + 7) >> 3 << 3) + rowoff;
    for (; r < to; r += 8) {
        const int i = r * WORDS + word;
        const unsigned A = bits[i];
        #pragma unroll
        for (int j = 0; j < 3; ++j) {
            const int R = RS[3 * G + j];
            const int C = CS[3 * G + j];
            const int bi = i + R * WORDS;
            unsigned B;
            if (C > 0)       B = __funnelshift_r(bits[bi], bits[bi + 1], C);
            else if (C < 0)  B = __funnelshift_l(bits[bi - 1], bits[bi], -C);
            else             B = bits[bi];

            unsigned m = 0xffffffffu;
            if (C > 0 && lastw)  m = 0xffffffffu >> C;
            if (C < 0 && firstw) m = 0xffffffffu << (-C);
            if (r >= rl[R]) m = 0u;           // last-slab row clip

            acc[j] += (unsigned)(__popc((A ^ B) & m) << 16)
                    |  (unsigned)__popc((A & B) & m);
        }
    }
}

extern __shared__ unsigned char dynsmem[];

__global__ __launch_bounds__(NTH, 3)
void glcm_tma(const float* __restrict__ in, float* __restrict__ out)
{
    constexpr int RS[NOFF] = {0, 1, 1, 1, 0, 2, 2, 2, 0, 3, 3, 3};
    constexpr int CS[NOFF] = {1, 1, 0, -1, 2, 2, 0, -2, 3, 3, 0, -3};

    float*    s_buf  = reinterpret_cast<float*>(dynsmem);          // NSTAGE*16KB
    unsigned* s_bits = reinterpret_cast<unsigned*>(dynsmem + NSTAGE * CBYTES);
    __shared__ unsigned long long s_mbar[NSTAGE];
    __shared__ int s_diff[NOFF];
    __shared__ int s_n11[NOFF];
    __shared__ int s_last;

    const int tid  = threadIdx.x;
    const int lane = tid & 31;
    const int warp = tid >> 5;
    const int r0   = blockIdx.x * SLAB;
    const int b    = blockIdx.y;
    const float* img = in + ((size_t)b * HH + r0) * WW;

    if (tid < NOFF) { s_diff[tid] = 0; s_n11[tid] = 0; }
    if (tid < NSTAGE)
        mbar_init((unsigned)__cvta_generic_to_shared(&s_mbar[tid]), 1u);
    __syncthreads();

    const unsigned sb  = (unsigned)__cvta_generic_to_shared(s_buf);
    const unsigned mb0 = (unsigned)__cvta_generic_to_shared(&s_mbar[0]);

    // ---- prologue: issue chunks 0..NSTAGE-1 via TMA bulk -------------------
    if (tid == 0) {
        #pragma unroll
        for (int s = 0; s < NSTAGE; ++s) {
            mbar_expect_tx(mb0 + 8u * s, CBYTES);
            bulk_g2s(sb + s * CBYTES, img + s * CFLOATS, CBYTES, mb0 + 8u * s);
        }
    }

    // ---- halo pack (rows SLAB..SLAB+2), plain LDG; skipped for last slab ---
    if (r0 + SLAB < HH) {
        for (int t = warp; t < HALO * WORDS; t += NTH / 32) {
            const int row = t >> 4, blk = t & 15;
            float v = img[(SLAB + row) * WW + blk * 32 + lane];
            unsigned bal = __ballot_sync(0xffffffffu, v > 0.0f);
            if (lane == 0) s_bits[(SLAB + row) * WORDS + blk] = bal;
        }
    }

    int rl[4];
    #pragma unroll
    for (int R = 0; R < 4; ++R) rl[R] = min(SLAB, HH - R - r0);

    unsigned acc[3] = {0u, 0u, 0u};
    const int worker = tid & 127;
    const int rowoff = worker >> 4;       // 0..7
    const int word   = worker & 15;       // 0..15
    const int grp    = tid >> 7;          // 0..3 (warp-uniform)

    const int prow  = warp >> 1;          // pack row within chunk (0..7)
    const int phalf = warp & 1;           // pack column half

    int from = 0;
    for (int c = 0; c < NCHUNK; ++c) {
        const int stage = c & (NSTAGE - 1);
        mbar_wait(mb0 + 8u * stage, (unsigned)((c / NSTAGE) & 1));

        // pack chunk c: 16 warps x (8 rows x 2 halves), 8 ballots each
        const float* bufc = s_buf + stage * CFLOATS;
        unsigned b4[4];
        #pragma unroll
        for (int j = 0; j < 8; ++j) {
            float v = bufc[prow * WW + phalf * 256 + j * 32 + lane];
            b4[j & 3] = __ballot_sync(0xffffffffu, v > 0.0f);
            if ((j & 3) == 3 && lane == 0)
                *reinterpret_cast<uint4*>(
                    &s_bits[(c * CROWS + prow) * WORDS + phalf * 8 + (j - 3)])
                    = make_uint4(b4[0], b4[1], b4[2], b4[3]);
        }
        __syncthreads();                  // bits(c) ready; buffer slot free

        // reissue the freed stage for chunk c+NSTAGE (before count -> overlap)
        if (tid == 0 && c + NSTAGE < NCHUNK) {
            mbar_expect_tx(mb0 + 8u * stage, CBYTES);
            bulk_g2s(sb + stage * CBYTES, img + (c + NSTAGE) * CFLOATS,
                     CBYTES, mb0 + 8u * stage);
        }

        // count newly-complete a-rows (need b-rows up to +3)
        const int to = (c == NCHUNK - 1) ? SLAB : c * CROWS + CROWS - HALO;
        if      (grp == 0) count_window<0>(s_bits, from, to, rowoff, word, rl, acc);
        else if (grp == 1) count_window<1>(s_bits, from, to, rowoff, word, rl, acc);
        else if (grp == 2) count_window<2>(s_bits, from, to, rowoff, word, rl, acc);
        else               count_window<3>(s_bits, from, to, rowoff, word, rl, acc);
        from = to;
    }

    // ---- reduce: warp -> block -> global ------------------------------------
    #pragma unroll
    for (int j = 0; j < 3; ++j) {
        unsigned v = __reduce_add_sync(0xffffffffu, acc[j]);
        if (lane == 0) {
            atomicAdd(&s_diff[3 * grp + j], (int)(v >> 16));
            atomicAdd(&s_n11[3 * grp + j],  (int)(v & 0xffffu));
        }
    }
    __syncthreads();

    if (tid < NOFF) {
        atomicAdd(&g_cnt[(b * NOFF + tid) * 2 + 0], s_diff[tid]);
        atomicAdd(&g_cnt[(b * NOFF + tid) * 2 + 1], s_n11[tid]);
    }

    // ---- last slab-block of this image finalizes ----------------------------
    if (tid == 0) {
        __threadfence();
        unsigned t = atomicAdd(&g_arrive[b], 1u);
        s_last = (t == SLABS - 1);
    }
    __syncthreads();

    if (s_last && tid < NOFF) {
        const int idx  = b * NOFF + tid;
        const int diff = atomicExch(&g_cnt[idx * 2 + 0], 0);   // read + reset
        const int n11  = atomicExch(&g_cnt[idx * 2 + 1], 0);
        if (tid == 0) atomicExch(&g_arrive[b], 0u);

        const int R  = RS[tid];
        const int Ca = CS[tid] < 0 ? -CS[tid] : CS[tid];
        const int N  = (HH - R) * (WW - Ca);
        const int n00 = N - n11 - diff;

        const float inv = 1.0f / (float)(2 * N - 4 * n00);
        float* o = out + (size_t)b * (NOFF * 4) + tid * 4;
        o[0] = (float)(4 * n00) * inv;
        const float v1 = (float)(2 * diff - 4 * n00) * inv;
        o[1] = v1;
        o[2] = v1;
        o[3] = (float)(2 * (N - 2 * diff)) * inv;
    }
}

extern "C" void kernel_launch(void* const* d_in, const int* in_sizes, int n_in,
                              void* d_out, int out_size)
{
    (void)n_in; (void)out_size;
    const int batch = in_sizes[0] / (HH * WW);    // 128
    const int smem = NSTAGE * CBYTES + BITS_WORDS * 4;   // ~72.6 KB
    cudaFuncSetAttribute(glcm_tma, cudaFuncAttributeMaxDynamicSharedMemorySize, smem);
    dim3 grid(SLABS, batch);                      // 4 x 128 = 512 blocks
    glcm_tma<<<grid, NTH, smem>>>((const float*)d_in[0], (float*)d_out);
}

// round 10
// speedup vs baseline: 1.1786x; 1.1786x over previous
#include <cuda_runtime.h>
#include <cstdint>

#define HH 512
#define WW 512
#define WORDS 16
#define SLAB 128
#define HALO 3
#define NTH 512
#define NWARPS 16
#define NOFF 12
#define SLABS (HH / SLAB)
#define MAXB 128
#define BITS_WORDS ((SLAB + HALO) * WORDS + WORDS)   // 2112 incl. guard

// zero-initialized; every use paired with a reset -> deterministic graph replays
__device__ int g_cnt[MAXB * NOFF * 2];     // [image][offset]{diff, n11}
__device__ unsigned g_arrive[MAXB];

// evaluate all 12 offsets for bit-word (r, w)
__device__ __forceinline__ void eval12(const unsigned* __restrict__ bits,
                                       int r, int w,
                                       const int* __restrict__ rl,
                                       unsigned* __restrict__ acc)
{
    constexpr int RS[NOFF] = {0, 1, 1, 1, 0, 2, 2, 2, 0, 3, 3, 3};
    constexpr int CS[NOFF] = {1, 1, 0, -1, 2, 2, 0, -2, 3, 3, 0, -3};
    const bool firstw = (w == 0);
    const bool lastw  = (w == WORDS - 1);
    const int i = r * WORDS + w;
    const unsigned A = bits[i];

    #pragma unroll
    for (int o = 0; o < NOFF; ++o) {
        const int R = RS[o];
        const int C = CS[o];
        const int bi = i + R * WORDS;
        unsigned B;
        if (C > 0)       B = __funnelshift_r(bits[bi], bits[bi + 1], C);
        else if (C < 0)  B = __funnelshift_l(bits[bi - 1], bits[bi], -C);
        else             B = bits[bi];

        unsigned m = 0xffffffffu;
        if (C > 0 && lastw)  m = 0xffffffffu >> C;
        if (C < 0 && firstw) m = 0xffffffffu << (-C);
        if (r >= rl[R]) m = 0u;              // last-slab row clip

        acc[o] += (unsigned)(__popc((A ^ B) & m) << 16)
                |  (unsigned)__popc((A & B) & m);
    }
}

__global__ __launch_bounds__(NTH, 3)
void glcm_free(const float* __restrict__ in, float* __restrict__ out)
{
    constexpr int RS[NOFF] = {0, 1, 1, 1, 0, 2, 2, 2, 0, 3, 3, 3};
    constexpr int CS[NOFF] = {1, 1, 0, -1, 2, 2, 0, -2, 3, 3, 0, -3};

    __shared__ unsigned bits[BITS_WORDS];
    __shared__ int s_diff[NOFF];
    __shared__ int s_n11[NOFF];
    __shared__ int s_last;

    const int tid  = threadIdx.x;
    const int lane = tid & 31;
    const int warp = tid >> 5;
    const int r0   = blockIdx.x * SLAB;
    const int b    = blockIdx.y;
    const float* img = in + ((size_t)b * HH + r0) * WW;

    if (tid < NOFF) { s_diff[tid] = 0; s_n11[tid] = 0; }
    if (tid == 0) bits[(SLAB + HALO) * WORDS] = 0u;   // guard word

    int rl[4];
    #pragma unroll
    for (int R = 0; R < 4; ++R) rl[R] = min(SLAB, HH - R - r0);

    // ---- pack own 8-row band: LDG + ballot -> SMEM bits (no barriers) -------
    const int base = warp * 8;
    #pragma unroll 2
    for (int j = 0; j < 8; ++j) {
        const float* rp = img + (base + j) * WW + lane;
        unsigned b4[4];
        #pragma unroll
        for (int w = 0; w < WORDS; ++w) {
            float v = rp[w * 32];
            b4[w & 3] = __ballot_sync(0xffffffffu, v > 0.0f);
            if ((w & 3) == 3 && lane == 0)
                *reinterpret_cast<uint4*>(&bits[(base + j) * WORDS + (w - 3)])
                    = make_uint4(b4[0], b4[1], b4[2], b4[3]);
        }
    }
    // warps 0..2 pack the cross-slab halo rows (skipped for last slab)
    if (warp < HALO && r0 + SLAB < HH) {
        const float* rp = img + (SLAB + warp) * WW + lane;
        unsigned b4[4];
        #pragma unroll
        for (int w = 0; w < WORDS; ++w) {
            float v = rp[w * 32];
            b4[w & 3] = __ballot_sync(0xffffffffu, v > 0.0f);
            if ((w & 3) == 3 && lane == 0)
                *reinterpret_cast<uint4*>(&bits[(SLAB + warp) * WORDS + (w - 3)])
                    = make_uint4(b4[0], b4[1], b4[2], b4[3]);
        }
    }
    __syncwarp();    // order STS (lane 0) before LDS (all lanes), warp scope

    // ---- own-band count: a-rows base..base+4 (self-contained, no sync) ------
    unsigned acc[NOFF];
    #pragma unroll
    for (int o = 0; o < NOFF; ++o) acc[o] = 0;

    for (int e = lane; e < 5 * WORDS; e += 32)
        eval12(bits, base + (e >> 4), e & 15, rl, acc);

    __syncthreads();   // the ONLY block barrier in the hot path

    // ---- deferred boundary rows: r % 8 in {5,6,7}, all bands ----------------
    for (int idx = tid; idx < NWARPS * 3 * WORDS; idx += NTH) {
        const int dr = idx >> 4;            // 0..47
        const int q  = dr / 3;
        const int rr = dr - 3 * q;
        eval12(bits, 8 * q + 5 + rr, idx & 15, rl, acc);
    }

    // ---- reduce: warp -> block -> global -------------------------------------
    #pragma unroll
    for (int o = 0; o < NOFF; ++o) {
        unsigned v = __reduce_add_sync(0xffffffffu, acc[o]);
        if (lane == 0) {
            atomicAdd(&s_diff[o], (int)(v >> 16));
            atomicAdd(&s_n11[o],  (int)(v & 0xffffu));
        }
    }
    __syncthreads();

    if (tid < NOFF) {
        atomicAdd(&g_cnt[(b * NOFF + tid) * 2 + 0], s_diff[tid]);
        atomicAdd(&g_cnt[(b * NOFF + tid) * 2 + 1], s_n11[tid]);
    }

    // ---- last slab-block of this image finalizes -----------------------------
    if (tid == 0) {
        __threadfence();
        unsigned t = atomicAdd(&g_arrive[b], 1u);
        s_last = (t == SLABS - 1);
    }
    __syncthreads();

    if (s_last && tid < NOFF) {
        const int idx  = b * NOFF + tid;
        const int diff = atomicExch(&g_cnt[idx * 2 + 0], 0);   // read + reset
        const int n11  = atomicExch(&g_cnt[idx * 2 + 1], 0);
        if (tid == 0) atomicExch(&g_arrive[b], 0u);

        const int R  = RS[tid];
        const int Ca = CS[tid] < 0 ? -CS[tid] : CS[tid];
        const int N  = (HH - R) * (WW - Ca);
        const int n00 = N - n11 - diff;

        const float inv = 1.0f / (float)(2 * N - 4 * n00);
        float* o = out + (size_t)b * (NOFF * 4) + tid * 4;
        o[0] = (float)(4 * n00) * inv;
        const float v1 = (float)(2 * diff - 4 * n00) * inv;
        o[1] = v1;
        o[2] = v1;
        o[3] = (float)(2 * (N - 2 * diff)) * inv;
    }
}

extern "C" void kernel_launch(void* const* d_in, const int* in_sizes, int n_in,
                              void* d_out, int out_size)
{
    (void)n_in; (void)out_size;
    const int batch = in_sizes[0] / (HH * WW);    // 128
    dim3 grid(SLABS, batch);                      // 4 x 128 = 512 blocks
    glcm_free<<<grid, NTH>>>((const float*)d_in[0], (float*)d_out);
}